// round 4
// baseline (speedup 1.0000x reference)
#include <cuda_runtime.h>
#include <cuda_bf16.h>
#include <mma.h>

using namespace nvcuda;

// EdgeConv: message MLP over edges + mean-aggregate + update MLP + residual.
// Inputs: x(N,64) f32, edge_index(2,E) i32, edge_attr(E,16) f32,
//   W1(144,64), b1(64), W2(64,64), b2(64), Wu(128,64), bu(64) f32.
// Output: (N,64) f32.
//
// R4: counting-sort edges by dst; edge kernel consumes sorted edges and does
// run-grouped register reduction -> ~10x fewer L2 atomic f32 ops.

#define ND      64
#define EDIM    16
#define HID     64
#define MSGIN   144   // 2*ND + EDIM
#define TILE_N  64
#define MAXN    100000
#define MAXE    1600000

#define LDIN_H  168   // bf16 In rows (336B)
#define LDW_H   88    // bf16 weight/H rows (176B)
#define LDSC_F  84    // f32 scratch rows (aliases In)
#define LDB_F   80    // bias tile f32

// Scratch (device globals: no allocation allowed)
__device__ float g_agg[(size_t)MAXN * HID];
__device__ float g_cnt[MAXN];
__device__ int   g_hist[MAXN];
__device__ int   g_off[MAXN];
__device__ int   g_cur[MAXN];
__device__ int   g_blk[256];
__device__ int   g_srcS[MAXE];
__device__ int   g_dstS[MAXE];
__device__ int   g_eidS[MAXE];

// ---------------------------------------------------------------------------
__global__ void zero_kernel(int N) {
    long long i = (long long)blockIdx.x * blockDim.x + threadIdx.x;
    long long stride = (long long)gridDim.x * blockDim.x;
    float4* a4 = reinterpret_cast<float4*>(g_agg);
    long long n4 = (long long)N * (HID / 4);
    float4 z = make_float4(0.f, 0.f, 0.f, 0.f);
    for (long long j = i; j < n4; j += stride) a4[j] = z;
    for (long long j = i; j < N; j += stride) g_hist[j] = 0;
}

// ---------------------------------------------------------------------------
__global__ void hist_kernel(const int* __restrict__ eidx, int E) {
    const int* dstp = eidx + E;
    int i = blockIdx.x * blockDim.x + threadIdx.x;
    int stride = gridDim.x * blockDim.x;
    for (int e = i; e < E; e += stride)
        atomicAdd(&g_hist[dstp[e]], 1);
}

// Exclusive scan over n bins, 1024 elems per block (256 thr x 4).
__global__ void scan1_kernel(int n) {
    __shared__ int sh[256];
    const int tid = threadIdx.x;
    const int base = blockIdx.x * 1024 + tid * 4;
    int v[4];
#pragma unroll
    for (int i = 0; i < 4; i++) v[i] = (base + i < n) ? g_hist[base + i] : 0;
    int tsum = v[0] + v[1] + v[2] + v[3];
    sh[tid] = tsum;
    __syncthreads();
    for (int off = 1; off < 256; off <<= 1) {
        int t = (tid >= off) ? sh[tid - off] : 0;
        __syncthreads();
        sh[tid] += t;
        __syncthreads();
    }
    int run = sh[tid] - tsum;   // exclusive within block
    if (tid == 255) g_blk[blockIdx.x] = sh[255];
#pragma unroll
    for (int i = 0; i < 4; i++) {
        if (base + i < n) g_off[base + i] = run;
        run += v[i];
    }
}

__global__ void scan2_kernel(int nb) {
    __shared__ int sh[256];
    const int tid = threadIdx.x;
    int v = (tid < nb) ? g_blk[tid] : 0;
    sh[tid] = v;
    __syncthreads();
    for (int off = 1; off < 256; off <<= 1) {
        int t = (tid >= off) ? sh[tid - off] : 0;
        __syncthreads();
        sh[tid] += t;
        __syncthreads();
    }
    if (tid < nb) g_blk[tid] = sh[tid] - v;   // exclusive
}

__global__ void scan3_kernel(int n) {
    int i = blockIdx.x * blockDim.x + threadIdx.x;
    int stride = gridDim.x * blockDim.x;
    for (int j = i; j < n; j += stride) {
        int o = g_off[j] + g_blk[j >> 10];
        g_off[j] = o;
        g_cur[j] = o;
        g_cnt[j] = (float)g_hist[j];
    }
}

__global__ void reorder_kernel(const int* __restrict__ eidx, int E) {
    const int* srcp = eidx;
    const int* dstp = eidx + E;
    int i = blockIdx.x * blockDim.x + threadIdx.x;
    int stride = gridDim.x * blockDim.x;
    for (int e = i; e < E; e += stride) {
        int d = dstp[e];
        int p = atomicAdd(&g_cur[d], 1);
        g_srcS[p] = srcp[e];
        g_dstS[p] = d;
        g_eidS[p] = e;
    }
}

// ---------------------------------------------------------------------------
// Edge kernel (bf16 WMMA 16x16x16), dst-sorted edges. 8 warps/CTA, each warp
// owns 32-edge tiles: gather -> GEMM1(K=144)+ReLU -> GEMM2(K=64, reg weights)
// -> run-grouped reduction -> few atomics.
// ---------------------------------------------------------------------------
__global__ void __launch_bounds__(256, 1)
edge_kernel(const float* __restrict__ x, const float* __restrict__ ea,
            const float* __restrict__ W1, const float* __restrict__ b1,
            const float* __restrict__ W2, int E, int nwt) {
    extern __shared__ __align__(16) char smraw[];
    __nv_bfloat16* sW1h = reinterpret_cast<__nv_bfloat16*>(smraw);             // 144*88
    __nv_bfloat16* sW2h = sW1h + MSGIN * LDW_H;                                // 64*88
    float*         sB1T = reinterpret_cast<float*>(sW2h + HID * LDW_H);        // 16*80
    __nv_bfloat16* sInH = reinterpret_cast<__nv_bfloat16*>(sB1T + 16 * LDB_F); // 256*168
    __nv_bfloat16* sHh  = sInH + 256 * LDIN_H;                                 // 256*88
    int*           sDst = reinterpret_cast<int*>(sHh + 256 * LDW_H);           // 256

    const int tid = threadIdx.x;

    for (int i = tid; i < MSGIN * HID; i += 256) {
        int k = i >> 6, n = i & 63;
        sW1h[k * LDW_H + n] = __float2bfloat16_rn(W1[i]);
    }
    for (int i = tid; i < HID * HID; i += 256) {
        int k = i >> 6, n = i & 63;
        sW2h[k * LDW_H + n] = __float2bfloat16_rn(W2[i]);
    }
    for (int i = tid; i < 16 * HID; i += 256) {
        int r = i >> 6, c = i & 63;
        sB1T[r * LDB_F + c] = b1[c];
    }
    __syncthreads();

    const int wid  = tid >> 5;
    const int lane = tid & 31;
    const int r0   = wid * 32;
    const int gw   = blockIdx.x * 8 + wid;
    const int gstride = gridDim.x * 8;

    __nv_bfloat16* myInH = sInH + r0 * LDIN_H;
    float*         myScr = reinterpret_cast<float*>(myInH);   // aliases In
    __nv_bfloat16* myHh  = sHh + r0 * LDW_H;
    int*           myDst = sDst + r0;

    // GEMM2 weights register-resident: 4 k-steps x 4 n-frags
    wmma::fragment<wmma::matrix_b, 16, 16, 16, __nv_bfloat16, wmma::row_major> w2f[4][4];
#pragma unroll
    for (int k = 0; k < 4; k++)
#pragma unroll
        for (int j = 0; j < 4; j++)
            wmma::load_matrix_sync(w2f[k][j], sW2h + (k * 16) * LDW_H + j * 16, LDW_H);

    for (int t = gw; t < nwt; t += gstride) {
        const int e0 = t * 32;

        // ---- gather (sorted): coalesced index loads; x[dst] runs hit L1 ----
        {
            const int e = e0 + lane;
            uint4* rp4 = reinterpret_cast<uint4*>(myInH + lane * LDIN_H);
            if (e < E) {
                const int s   = g_srcS[e];
                const int d   = g_dstS[e];
                const int eid = g_eidS[e];
                myDst[lane] = d;
                const float4* xs = reinterpret_cast<const float4*>(x + (size_t)s * ND);
                const float4* xd = reinterpret_cast<const float4*>(x + (size_t)d * ND);
#pragma unroll
                for (int i = 0; i < 8; i++) {
                    float4 a = xs[2 * i], b = xs[2 * i + 1];
                    __nv_bfloat162 p0 = __floats2bfloat162_rn(a.x, a.y);
                    __nv_bfloat162 p1 = __floats2bfloat162_rn(a.z, a.w);
                    __nv_bfloat162 p2 = __floats2bfloat162_rn(b.x, b.y);
                    __nv_bfloat162 p3 = __floats2bfloat162_rn(b.z, b.w);
                    uint4 u;
                    u.x = *reinterpret_cast<unsigned*>(&p0);
                    u.y = *reinterpret_cast<unsigned*>(&p1);
                    u.z = *reinterpret_cast<unsigned*>(&p2);
                    u.w = *reinterpret_cast<unsigned*>(&p3);
                    rp4[i] = u;
                }
#pragma unroll
                for (int i = 0; i < 8; i++) {
                    float4 a = xd[2 * i], b = xd[2 * i + 1];
                    __nv_bfloat162 p0 = __floats2bfloat162_rn(a.x, a.y);
                    __nv_bfloat162 p1 = __floats2bfloat162_rn(a.z, a.w);
                    __nv_bfloat162 p2 = __floats2bfloat162_rn(b.x, b.y);
                    __nv_bfloat162 p3 = __floats2bfloat162_rn(b.z, b.w);
                    uint4 u;
                    u.x = *reinterpret_cast<unsigned*>(&p0);
                    u.y = *reinterpret_cast<unsigned*>(&p1);
                    u.z = *reinterpret_cast<unsigned*>(&p2);
                    u.w = *reinterpret_cast<unsigned*>(&p3);
                    rp4[8 + i] = u;
                }
                const float4* ap = reinterpret_cast<const float4*>(ea + (size_t)eid * EDIM);
#pragma unroll
                for (int i = 0; i < 2; i++) {
                    float4 a = ap[2 * i], b = ap[2 * i + 1];
                    __nv_bfloat162 p0 = __floats2bfloat162_rn(a.x, a.y);
                    __nv_bfloat162 p1 = __floats2bfloat162_rn(a.z, a.w);
                    __nv_bfloat162 p2 = __floats2bfloat162_rn(b.x, b.y);
                    __nv_bfloat162 p3 = __floats2bfloat162_rn(b.z, b.w);
                    uint4 u;
                    u.x = *reinterpret_cast<unsigned*>(&p0);
                    u.y = *reinterpret_cast<unsigned*>(&p1);
                    u.z = *reinterpret_cast<unsigned*>(&p2);
                    u.w = *reinterpret_cast<unsigned*>(&p3);
                    rp4[16 + i] = u;
                }
            } else {
                uint4 z = make_uint4(0, 0, 0, 0);
#pragma unroll
                for (int i = 0; i < 18; i++) rp4[i] = z;
                myDst[lane] = -1;
            }
        }
        __syncwarp();

        // ---- GEMM1: (32 x 144) @ (144 x 64), b1 preloaded in C ----
        wmma::fragment<wmma::accumulator, 16, 16, 16, float> c[2][4];
        wmma::fragment<wmma::matrix_a, 16, 16, 16, __nv_bfloat16, wmma::row_major> af[2];
        wmma::fragment<wmma::matrix_b, 16, 16, 16, __nv_bfloat16, wmma::row_major> bf;
#pragma unroll
        for (int i = 0; i < 2; i++)
#pragma unroll
            for (int j = 0; j < 4; j++)
                wmma::load_matrix_sync(c[i][j], sB1T + j * 16, LDB_F, wmma::mem_row_major);
#pragma unroll
        for (int k = 0; k < MSGIN / 16; k++) {
            wmma::load_matrix_sync(af[0], myInH + k * 16, LDIN_H);
            wmma::load_matrix_sync(af[1], myInH + 16 * LDIN_H + k * 16, LDIN_H);
#pragma unroll
            for (int j = 0; j < 4; j++) {
                wmma::load_matrix_sync(bf, sW1h + (k * 16) * LDW_H + j * 16, LDW_H);
                wmma::mma_sync(c[0][j], af[0], bf, c[0][j]);
                wmma::mma_sync(c[1][j], af[1], bf, c[1][j]);
            }
        }
#pragma unroll
        for (int i = 0; i < 2; i++)
#pragma unroll
            for (int j = 0; j < 4; j++) {
#pragma unroll
                for (int q = 0; q < c[i][j].num_elements; q++)
                    c[i][j].x[q] = fmaxf(c[i][j].x[q], 0.f);
                wmma::store_matrix_sync(myScr + (i * 16) * LDSC_F + j * 16, c[i][j],
                                        LDSC_F, wmma::mem_row_major);
            }
        __syncwarp();

        // f32 -> bf16 H
        {
            const float4* srow = reinterpret_cast<const float4*>(myScr + lane * LDSC_F);
            uint4* hrow = reinterpret_cast<uint4*>(myHh + lane * LDW_H);
#pragma unroll
            for (int i = 0; i < 8; i++) {
                float4 a = srow[2 * i], b = srow[2 * i + 1];
                __nv_bfloat162 p0 = __floats2bfloat162_rn(a.x, a.y);
                __nv_bfloat162 p1 = __floats2bfloat162_rn(a.z, a.w);
                __nv_bfloat162 p2 = __floats2bfloat162_rn(b.x, b.y);
                __nv_bfloat162 p3 = __floats2bfloat162_rn(b.z, b.w);
                uint4 u;
                u.x = *reinterpret_cast<unsigned*>(&p0);
                u.y = *reinterpret_cast<unsigned*>(&p1);
                u.z = *reinterpret_cast<unsigned*>(&p2);
                u.w = *reinterpret_cast<unsigned*>(&p3);
                hrow[i] = u;
            }
        }
        __syncwarp();

        // ---- GEMM2: (32 x 64) @ (64 x 64), weights in registers, C=0 ----
#pragma unroll
        for (int i = 0; i < 2; i++)
#pragma unroll
            for (int j = 0; j < 4; j++)
                wmma::fill_fragment(c[i][j], 0.f);
#pragma unroll
        for (int k = 0; k < HID / 16; k++) {
            wmma::load_matrix_sync(af[0], myHh + k * 16, LDW_H);
            wmma::load_matrix_sync(af[1], myHh + 16 * LDW_H + k * 16, LDW_H);
#pragma unroll
            for (int j = 0; j < 4; j++) {
                wmma::mma_sync(c[0][j], af[0], w2f[k][j], c[0][j]);
                wmma::mma_sync(c[1][j], af[1], w2f[k][j], c[1][j]);
            }
        }
#pragma unroll
        for (int i = 0; i < 2; i++)
#pragma unroll
            for (int j = 0; j < 4; j++)
                wmma::store_matrix_sync(myScr + (i * 16) * LDSC_F + j * 16, c[i][j],
                                        LDSC_F, wmma::mem_row_major);
        __syncwarp();

        // ---- run-grouped reduction: lane owns cols {lane, lane+32} ----
        {
            float a0 = 0.f, a1 = 0.f;
            int cur = -1;
#pragma unroll 4
            for (int r = 0; r < 32; r++) {
                const int d = myDst[r];   // -1 on tail
                if (d != cur) {
                    if (cur >= 0) {
                        atomicAdd(&g_agg[(size_t)cur * HID + lane], a0);
                        atomicAdd(&g_agg[(size_t)cur * HID + 32 + lane], a1);
                    }
                    a0 = 0.f; a1 = 0.f; cur = d;
                }
                if (d >= 0) {
                    a0 += myScr[r * LDSC_F + lane];
                    a1 += myScr[r * LDSC_F + 32 + lane];
                }
            }
            if (cur >= 0) {
                atomicAdd(&g_agg[(size_t)cur * HID + lane], a0);
                atomicAdd(&g_agg[(size_t)cur * HID + 32 + lane], a1);
            }
        }
        __syncwarp();
    }
}

// ---------------------------------------------------------------------------
// Node kernel: fp32 exact; mean + b2 folded into aggregate load.
// ---------------------------------------------------------------------------
#define FMA16(ACC, AV, BV)                                                    \
  ACC[0][0] = fmaf(AV.x, BV.x, ACC[0][0]);                                    \
  ACC[0][1] = fmaf(AV.x, BV.y, ACC[0][1]);                                    \
  ACC[0][2] = fmaf(AV.x, BV.z, ACC[0][2]);                                    \
  ACC[0][3] = fmaf(AV.x, BV.w, ACC[0][3]);                                    \
  ACC[1][0] = fmaf(AV.y, BV.x, ACC[1][0]);                                    \
  ACC[1][1] = fmaf(AV.y, BV.y, ACC[1][1]);                                    \
  ACC[1][2] = fmaf(AV.y, BV.z, ACC[1][2]);                                    \
  ACC[1][3] = fmaf(AV.y, BV.w, ACC[1][3]);                                    \
  ACC[2][0] = fmaf(AV.z, BV.x, ACC[2][0]);                                    \
  ACC[2][1] = fmaf(AV.z, BV.y, ACC[2][1]);                                    \
  ACC[2][2] = fmaf(AV.z, BV.z, ACC[2][2]);                                    \
  ACC[2][3] = fmaf(AV.z, BV.w, ACC[2][3]);                                    \
  ACC[3][0] = fmaf(AV.w, BV.x, ACC[3][0]);                                    \
  ACC[3][1] = fmaf(AV.w, BV.y, ACC[3][1]);                                    \
  ACC[3][2] = fmaf(AV.w, BV.z, ACC[3][2]);                                    \
  ACC[3][3] = fmaf(AV.w, BV.w, ACC[3][3]);

__global__ void __launch_bounds__(256, 3)
node_kernel(const float* __restrict__ x, const float* __restrict__ Wu,
            const float* __restrict__ bu, const float* __restrict__ b2,
            float* __restrict__ out, int N, int ntiles) {
    extern __shared__ float smn[];
    float* sWu = smn;                     // [128][64]
    float* sIn = sWu + 2 * ND * HID;      // [128][64]
    float* sBu = sIn + 2 * ND * TILE_N;   // [64]
    float* sB2 = sBu + HID;               // [64]

    const int tid = threadIdx.x;
    for (int i = tid; i < 2 * ND * HID; i += 256) sWu[i] = Wu[i];
    if (tid < HID) { sBu[tid] = bu[tid]; sB2[tid] = b2[tid]; }
    __syncthreads();

    const int tx = tid & 15;
    const int ty = tid >> 4;
    const int q  = tid & 3;
    const int ng = tid >> 2;

    for (int tile = blockIdx.x; tile < ntiles; tile += gridDim.x) {
        const int n0 = tile * TILE_N;
        {
            const int n = n0 + ng;
            if (n < N) {
                const float cnt = g_cnt[n];
                const float inv = 1.0f / (cnt + 1e-6f);
                const float f   = cnt * inv;
                const float4* xr = reinterpret_cast<const float4*>(x + (size_t)n * ND);
                const float4* ar = reinterpret_cast<const float4*>(g_agg + (size_t)n * HID);
#pragma unroll
                for (int i = 0; i < 4; i++) {
                    const int f4 = q + 4 * i;
                    const int k  = f4 * 4;
                    float4 v = xr[f4];
                    sIn[(k + 0) * TILE_N + ng] = v.x;
                    sIn[(k + 1) * TILE_N + ng] = v.y;
                    sIn[(k + 2) * TILE_N + ng] = v.z;
                    sIn[(k + 3) * TILE_N + ng] = v.w;
                    float4 w = ar[f4];
                    sIn[(ND + k + 0) * TILE_N + ng] = w.x * inv + sB2[k + 0] * f;
                    sIn[(ND + k + 1) * TILE_N + ng] = w.y * inv + sB2[k + 1] * f;
                    sIn[(ND + k + 2) * TILE_N + ng] = w.z * inv + sB2[k + 2] * f;
                    sIn[(ND + k + 3) * TILE_N + ng] = w.w * inv + sB2[k + 3] * f;
                }
            }
        }
        __syncthreads();

        float acc[4][4];
#pragma unroll
        for (int a = 0; a < 4; a++)
#pragma unroll
            for (int b = 0; b < 4; b++) acc[a][b] = 0.f;

#pragma unroll 8
        for (int k = 0; k < 2 * ND; k++) {
            float4 av = *reinterpret_cast<const float4*>(&sIn[k * TILE_N + tx * 4]);
            float4 bv = *reinterpret_cast<const float4*>(&sWu[k * HID + ty * 4]);
            FMA16(acc, av, bv)
        }

#pragma unroll
        for (int ei = 0; ei < 4; ei++) {
            const int n = n0 + tx * 4 + ei;
            if (n < N) {
                float4 o;
                float r;
                r = acc[ei][0] + sBu[ty * 4 + 0];
                o.x = sIn[(ty * 4 + 0) * TILE_N + tx * 4 + ei] + (r > 0.f ? r : 0.f);
                r = acc[ei][1] + sBu[ty * 4 + 1];
                o.y = sIn[(ty * 4 + 1) * TILE_N + tx * 4 + ei] + (r > 0.f ? r : 0.f);
                r = acc[ei][2] + sBu[ty * 4 + 2];
                o.z = sIn[(ty * 4 + 2) * TILE_N + tx * 4 + ei] + (r > 0.f ? r : 0.f);
                r = acc[ei][3] + sBu[ty * 4 + 3];
                o.w = sIn[(ty * 4 + 3) * TILE_N + tx * 4 + ei] + (r > 0.f ? r : 0.f);
                *reinterpret_cast<float4*>(out + (size_t)n * HID + ty * 4) = o;
            }
        }
        __syncthreads();
    }
}

// ---------------------------------------------------------------------------
extern "C" void kernel_launch(void* const* d_in, const int* in_sizes, int n_in,
                              void* d_out, int out_size) {
    const float* x   = (const float*)d_in[0];
    const int*   ei  = (const int*)d_in[1];
    const float* ea  = (const float*)d_in[2];
    const float* W1  = (const float*)d_in[3];
    const float* b1  = (const float*)d_in[4];
    const float* W2  = (const float*)d_in[5];
    const float* b2  = (const float*)d_in[6];
    const float* Wu  = (const float*)d_in[7];
    const float* bu  = (const float*)d_in[8];
    float* out = (float*)d_out;

    const int N = in_sizes[0] / ND;     // 100000
    const int E = in_sizes[2] / EDIM;   // 1600000

    const int smem_edge = (MSGIN * LDW_H + HID * LDW_H) * 2 + 16 * LDB_F * 4 +
                          256 * LDIN_H * 2 + 256 * LDW_H * 2 + 256 * 4;
    const int smem_node = (2 * ND * HID + 2 * ND * TILE_N + 2 * HID) * 4;

    cudaFuncSetAttribute(edge_kernel, cudaFuncAttributeMaxDynamicSharedMemorySize,
                         smem_edge);
    cudaFuncSetAttribute(node_kernel, cudaFuncAttributeMaxDynamicSharedMemorySize,
                         smem_node);

    const int nwt = (E + 31) / 32;
    const int ntiles = (N + TILE_N - 1) / TILE_N;
    const int nb1 = (N + 1023) / 1024;   // scan blocks (<= 256)

    zero_kernel<<<2048, 256>>>(N);
    hist_kernel<<<1024, 256>>>(ei, E);
    scan1_kernel<<<nb1, 256>>>(N);
    scan2_kernel<<<1, 256>>>(nb1);
    scan3_kernel<<<256, 256>>>(N);
    reorder_kernel<<<1024, 256>>>(ei, E);
    edge_kernel<<<148, 256, smem_edge>>>(x, ea, W1, b1, W2, E, nwt);
    node_kernel<<<456, 256, smem_node>>>(x, Wu, bu, b2, out, N, ntiles);
}

// round 6
// speedup vs baseline: 1.3808x; 1.3808x over previous
#include <cuda_runtime.h>
#include <cuda_bf16.h>
#include <cstdint>

// EdgeConv: message MLP over edges + mean-aggregate + update MLP + residual.
// Inputs: x(N,64) f32, edge_index(2,E) i32, edge_attr(E,16) f32,
//   W1(144,64), b1(64), W2(64,64), b2(64), Wu(128,64), bu(64) f32.
// Output: (N,64) f32.
//
// R6 (= R5 + missing <cstdint>): raw mma.m16n8k16 with register-resident
// GEMM1->GEMM2 handoff (accum fragment == next A fragment), 512 thr/CTA
// (16 warps), bf16 x precomputed.

#define ND      64
#define EDIM    16
#define HID     64
#define MSGIN   144   // 2*ND + EDIM
#define TILE_N  64
#define MAXN    100000

#define LDIN_H  168   // bf16 In row stride (336B) - conflict-free for ldmatrix
#define LDW_H   88    // bf16 weight row stride (176B) - conflict-free
#define LDSC_F  84    // f32 scratch stride aliasing In rows (336B)

// Scratch (device globals: no allocation allowed)
__device__ float         g_agg[(size_t)MAXN * HID];
__device__ float         g_cnt[MAXN];
__device__ __nv_bfloat16 g_xh[(size_t)MAXN * ND];

static __device__ __forceinline__ uint32_t s2u(const void* p) {
    return (uint32_t)__cvta_generic_to_shared(p);
}

static __device__ __forceinline__ void ldsm_x4(uint32_t addr, uint32_t& r0,
                                               uint32_t& r1, uint32_t& r2,
                                               uint32_t& r3) {
    asm volatile("ldmatrix.sync.aligned.m8n8.x4.shared.b16 {%0,%1,%2,%3}, [%4];"
                 : "=r"(r0), "=r"(r1), "=r"(r2), "=r"(r3) : "r"(addr));
}

static __device__ __forceinline__ void ldsm_x4t(uint32_t addr, uint32_t& r0,
                                                uint32_t& r1, uint32_t& r2,
                                                uint32_t& r3) {
    asm volatile("ldmatrix.sync.aligned.m8n8.x4.trans.shared.b16 {%0,%1,%2,%3}, [%4];"
                 : "=r"(r0), "=r"(r1), "=r"(r2), "=r"(r3) : "r"(addr));
}

static __device__ __forceinline__ void mma16816(float* c, uint32_t a0, uint32_t a1,
                                                uint32_t a2, uint32_t a3,
                                                uint32_t b0, uint32_t b1) {
    asm volatile(
        "mma.sync.aligned.m16n8k16.row.col.f32.bf16.bf16.f32 "
        "{%0,%1,%2,%3}, {%4,%5,%6,%7}, {%8,%9}, {%0,%1,%2,%3};"
        : "+f"(c[0]), "+f"(c[1]), "+f"(c[2]), "+f"(c[3])
        : "r"(a0), "r"(a1), "r"(a2), "r"(a3), "r"(b0), "r"(b1));
}

static __device__ __forceinline__ uint32_t cvt2(float lo, float hi) {
    __nv_bfloat162 p = __floats2bfloat162_rn(lo, hi);
    return *reinterpret_cast<uint32_t*>(&p);
}

// ---------------------------------------------------------------------------
__global__ void zero_kernel(int N) {
    long long i = (long long)blockIdx.x * blockDim.x + threadIdx.x;
    long long stride = (long long)gridDim.x * blockDim.x;
    float4* a4 = reinterpret_cast<float4*>(g_agg);
    long long n4 = (long long)N * (HID / 4);
    float4 z = make_float4(0.f, 0.f, 0.f, 0.f);
    for (long long j = i; j < n4; j += stride) a4[j] = z;
    for (long long j = i; j < N; j += stride) g_cnt[j] = 0.f;
}

__global__ void convx_kernel(const float* __restrict__ x, int N) {
    int i = blockIdx.x * blockDim.x + threadIdx.x;
    int stride = gridDim.x * blockDim.x;
    const int n8 = N * ND / 8;
    const float4* xin = reinterpret_cast<const float4*>(x);
    uint4* xo = reinterpret_cast<uint4*>(g_xh);
    for (int j = i; j < n8; j += stride) {
        float4 a = xin[2 * j], b = xin[2 * j + 1];
        uint4 u;
        u.x = cvt2(a.x, a.y); u.y = cvt2(a.z, a.w);
        u.z = cvt2(b.x, b.y); u.w = cvt2(b.z, b.w);
        xo[j] = u;
    }
}

// ---------------------------------------------------------------------------
// Edge kernel: 512 threads, 16 warps, 1 CTA/SM. Each warp: 32-edge tiles as
// two 16-row halves. Per half: gather -> GEMM1 (m16n8k16, K=144) ->
// bias+ReLU+cvt in regs -> GEMM2 (K=64) -> scratch -> float4 atomic scatter.
// ---------------------------------------------------------------------------
__global__ void __launch_bounds__(512, 1)
edge_kernel(const int* __restrict__ eidx, const float* __restrict__ ea,
            const float* __restrict__ W1, const float* __restrict__ b1,
            const float* __restrict__ W2, int E, int nwt) {
    extern __shared__ __align__(16) char smraw[];
    __nv_bfloat16* sW1h = reinterpret_cast<__nv_bfloat16*>(smraw);      // 144*88
    __nv_bfloat16* sW2h = sW1h + MSGIN * LDW_H;                         // 64*88
    __nv_bfloat16* sIn  = sW2h + HID * LDW_H;                           // 16w*32*168
    int*           sDst = reinterpret_cast<int*>(sIn + 16 * 32 * LDIN_H); // 512

    const int tid = threadIdx.x;
    for (int i = tid; i < MSGIN * HID; i += 512) {
        int k = i >> 6, n = i & 63;
        sW1h[k * LDW_H + n] = __float2bfloat16_rn(W1[i]);
    }
    for (int i = tid; i < HID * HID; i += 512) {
        int k = i >> 6, n = i & 63;
        sW2h[k * LDW_H + n] = __float2bfloat16_rn(W2[i]);
    }
    __syncthreads();

    const int wid  = tid >> 5;
    const int lane = tid & 31;
    const int gq   = lane >> 2;       // fragment row group
    const int tq   = lane & 3;        // fragment col group
    const int gw   = blockIdx.x * 16 + wid;
    const int gstride = gridDim.x * 16;

    const int* __restrict__ srcp = eidx;
    const int* __restrict__ dstp = eidx + E;

    __nv_bfloat16* myIn = sIn + wid * 32 * LDIN_H;
    float*         myScr = reinterpret_cast<float*>(myIn);   // row-aliased
    int*           myDst = sDst + wid * 32;

    // per-lane b1 bias pairs: ntile j covers cols 8j+2t, 8j+2t+1
    float2 bias1[8];
#pragma unroll
    for (int j = 0; j < 8; j++) {
        bias1[j].x = b1[8 * j + 2 * tq];
        bias1[j].y = b1[8 * j + 2 * tq + 1];
    }

    // ldmatrix lane-address bases (bytes)
    const uint32_t inBase = s2u(myIn) + (((lane & 15) * LDIN_H) + 8 * (lane >> 4)) * 2;
    const uint32_t w1Base = s2u(sW1h) + (((lane & 15) * LDW_H) + 8 * (lane >> 4)) * 2;
    const uint32_t w2Base = s2u(sW2h) + (((lane & 15) * LDW_H) + 8 * (lane >> 4)) * 2;

    for (int t = gw; t < nwt; t += gstride) {
        const int e0 = t * 32;
#pragma unroll
        for (int h = 0; h < 2; h++) {
            const int eb = e0 + h * 16;
            const int r0 = h * 16;

            // ---- gather: 2 lanes per edge ----
            {
                const int el = lane >> 1;
                const int part = lane & 1;
                const int e = eb + el;
                uint4* rp4 = reinterpret_cast<uint4*>(myIn + (r0 + el) * LDIN_H);
                if (e < E) {
                    if (part == 0) {
                        const int s = srcp[e];
                        const uint4* xs = reinterpret_cast<const uint4*>(g_xh + (size_t)s * ND);
#pragma unroll
                        for (int i = 0; i < 8; i++) rp4[i] = xs[i];
                        const float4* ap = reinterpret_cast<const float4*>(ea + (size_t)e * EDIM);
                        float4 a = ap[0], b = ap[1], c = ap[2], d = ap[3];
                        uint4 u;
                        u.x = cvt2(a.x, a.y); u.y = cvt2(a.z, a.w);
                        u.z = cvt2(b.x, b.y); u.w = cvt2(b.z, b.w);
                        rp4[16] = u;
                        u.x = cvt2(c.x, c.y); u.y = cvt2(c.z, c.w);
                        u.z = cvt2(d.x, d.y); u.w = cvt2(d.z, d.w);
                        rp4[17] = u;
                    } else {
                        const int d = dstp[e];
                        myDst[r0 + el] = d;
                        const uint4* xd = reinterpret_cast<const uint4*>(g_xh + (size_t)d * ND);
#pragma unroll
                        for (int i = 0; i < 8; i++) rp4[8 + i] = xd[i];
                    }
                } else {
                    uint4 z = make_uint4(0, 0, 0, 0);
                    if (part == 0) {
#pragma unroll
                        for (int i = 0; i < 8; i++) rp4[i] = z;
                        rp4[16] = z; rp4[17] = z;
                    } else {
#pragma unroll
                        for (int i = 0; i < 8; i++) rp4[8 + i] = z;
                        myDst[r0 + el] = -1;
                    }
                }
            }
            __syncwarp();

            // ---- GEMM1: (16 x 144) @ (144 x 64) ----
            float acc[8][4];
#pragma unroll
            for (int j = 0; j < 8; j++)
#pragma unroll
                for (int q = 0; q < 4; q++) acc[j][q] = 0.f;

            const uint32_t inH = inBase + r0 * LDIN_H * 2;
#pragma unroll
            for (int k = 0; k < MSGIN / 16; k++) {
                uint32_t a0, a1, a2, a3;
                ldsm_x4(inH + k * 32, a0, a1, a2, a3);
#pragma unroll
                for (int nb = 0; nb < 4; nb++) {
                    uint32_t p0, p1, p2, p3;
                    ldsm_x4t(w1Base + (k * 16 * LDW_H + nb * 16) * 2, p0, p1, p2, p3);
                    mma16816(acc[2 * nb],     a0, a1, a2, a3, p0, p1);
                    mma16816(acc[2 * nb + 1], a0, a1, a2, a3, p2, p3);
                }
            }

            // ---- bias + ReLU + cvt -> A fragments of GEMM2 (registers) ----
            uint32_t aH[16];
#pragma unroll
            for (int q = 0; q < 4; q++) {
                const int j0 = 2 * q, j1 = 2 * q + 1;
                aH[4 * q + 0] = cvt2(fmaxf(acc[j0][0] + bias1[j0].x, 0.f),
                                     fmaxf(acc[j0][1] + bias1[j0].y, 0.f));
                aH[4 * q + 1] = cvt2(fmaxf(acc[j0][2] + bias1[j0].x, 0.f),
                                     fmaxf(acc[j0][3] + bias1[j0].y, 0.f));
                aH[4 * q + 2] = cvt2(fmaxf(acc[j1][0] + bias1[j1].x, 0.f),
                                     fmaxf(acc[j1][1] + bias1[j1].y, 0.f));
                aH[4 * q + 3] = cvt2(fmaxf(acc[j1][2] + bias1[j1].x, 0.f),
                                     fmaxf(acc[j1][3] + bias1[j1].y, 0.f));
            }

            // ---- GEMM2: (16 x 64) @ (64 x 64) ----
#pragma unroll
            for (int j = 0; j < 8; j++)
#pragma unroll
                for (int q = 0; q < 4; q++) acc[j][q] = 0.f;
#pragma unroll
            for (int q = 0; q < 4; q++) {
#pragma unroll
                for (int nb = 0; nb < 4; nb++) {
                    uint32_t p0, p1, p2, p3;
                    ldsm_x4t(w2Base + (q * 16 * LDW_H + nb * 16) * 2, p0, p1, p2, p3);
                    mma16816(acc[2 * nb],     aH[4 * q + 0], aH[4 * q + 1],
                             aH[4 * q + 2], aH[4 * q + 3], p0, p1);
                    mma16816(acc[2 * nb + 1], aH[4 * q + 0], aH[4 * q + 1],
                             aH[4 * q + 2], aH[4 * q + 3], p2, p3);
                }
            }

            // ---- store to f32 scratch (aliases this half's In rows) ----
            {
                float* base0 = myScr + (r0 + gq) * LDSC_F + 2 * tq;
                float* base1 = myScr + (r0 + gq + 8) * LDSC_F + 2 * tq;
#pragma unroll
                for (int j = 0; j < 8; j++) {
                    *reinterpret_cast<float2*>(base0 + 8 * j) =
                        make_float2(acc[j][0], acc[j][1]);
                    *reinterpret_cast<float2*>(base1 + 8 * j) =
                        make_float2(acc[j][2], acc[j][3]);
                }
            }
            __syncwarp();

            // ---- float4 atomic scatter: 16 rows x 16 float4 ----
#pragma unroll
            for (int i = 0; i < 8; i++) {
                const int idx = lane + 32 * i;
                const int row = idx >> 4;
                const int c4  = idx & 15;
                const int d = myDst[r0 + row];
                if (d >= 0) {
                    float4 v = *reinterpret_cast<const float4*>(
                        myScr + (r0 + row) * LDSC_F + c4 * 4);
                    atomicAdd(reinterpret_cast<float4*>(
                        g_agg + (size_t)d * HID + c4 * 4), v);
                }
            }
            if (lane < 16) {
                const int d = myDst[r0 + lane];
                if (d >= 0) atomicAdd(&g_cnt[d], 1.0f);
            }
            __syncwarp();
        }
    }
}

// ---------------------------------------------------------------------------
// Node kernel: fp32 exact; mean + b2 folded into aggregate load.
// ---------------------------------------------------------------------------
#define FMA16(ACC, AV, BV)                                                    \
  ACC[0][0] = fmaf(AV.x, BV.x, ACC[0][0]);                                    \
  ACC[0][1] = fmaf(AV.x, BV.y, ACC[0][1]);                                    \
  ACC[0][2] = fmaf(AV.x, BV.z, ACC[0][2]);                                    \
  ACC[0][3] = fmaf(AV.x, BV.w, ACC[0][3]);                                    \
  ACC[1][0] = fmaf(AV.y, BV.x, ACC[1][0]);                                    \
  ACC[1][1] = fmaf(AV.y, BV.y, ACC[1][1]);                                    \
  ACC[1][2] = fmaf(AV.y, BV.z, ACC[1][2]);                                    \
  ACC[1][3] = fmaf(AV.y, BV.w, ACC[1][3]);                                    \
  ACC[2][0] = fmaf(AV.z, BV.x, ACC[2][0]);                                    \
  ACC[2][1] = fmaf(AV.z, BV.y, ACC[2][1]);                                    \
  ACC[2][2] = fmaf(AV.z, BV.z, ACC[2][2]);                                    \
  ACC[2][3] = fmaf(AV.z, BV.w, ACC[2][3]);                                    \
  ACC[3][0] = fmaf(AV.w, BV.x, ACC[3][0]);                                    \
  ACC[3][1] = fmaf(AV.w, BV.y, ACC[3][1]);                                    \
  ACC[3][2] = fmaf(AV.w, BV.z, ACC[3][2]);                                    \
  ACC[3][3] = fmaf(AV.w, BV.w, ACC[3][3]);

__global__ void __launch_bounds__(256, 3)
node_kernel(const float* __restrict__ x, const float* __restrict__ Wu,
            const float* __restrict__ bu, const float* __restrict__ b2,
            float* __restrict__ out, int N, int ntiles) {
    extern __shared__ float smn[];
    float* sWu = smn;                     // [128][64]
    float* sIn = sWu + 2 * ND * HID;      // [128][64]
    float* sBu = sIn + 2 * ND * TILE_N;   // [64]
    float* sB2 = sBu + HID;               // [64]

    const int tid = threadIdx.x;
    for (int i = tid; i < 2 * ND * HID; i += 256) sWu[i] = Wu[i];
    if (tid < HID) { sBu[tid] = bu[tid]; sB2[tid] = b2[tid]; }
    __syncthreads();

    const int tx = tid & 15;
    const int ty = tid >> 4;
    const int q  = tid & 3;
    const int ng = tid >> 2;

    for (int tile = blockIdx.x; tile < ntiles; tile += gridDim.x) {
        const int n0 = tile * TILE_N;
        {
            const int n = n0 + ng;
            if (n < N) {
                const float cnt = g_cnt[n];
                const float inv = 1.0f / (cnt + 1e-6f);
                const float f   = cnt * inv;
                const float4* xr = reinterpret_cast<const float4*>(x + (size_t)n * ND);
                const float4* ar = reinterpret_cast<const float4*>(g_agg + (size_t)n * HID);
#pragma unroll
                for (int i = 0; i < 4; i++) {
                    const int f4 = q + 4 * i;
                    const int k  = f4 * 4;
                    float4 v = xr[f4];
                    sIn[(k + 0) * TILE_N + ng] = v.x;
                    sIn[(k + 1) * TILE_N + ng] = v.y;
                    sIn[(k + 2) * TILE_N + ng] = v.z;
                    sIn[(k + 3) * TILE_N + ng] = v.w;
                    float4 w = ar[f4];
                    sIn[(ND + k + 0) * TILE_N + ng] = w.x * inv + sB2[k + 0] * f;
                    sIn[(ND + k + 1) * TILE_N + ng] = w.y * inv + sB2[k + 1] * f;
                    sIn[(ND + k + 2) * TILE_N + ng] = w.z * inv + sB2[k + 2] * f;
                    sIn[(ND + k + 3) * TILE_N + ng] = w.w * inv + sB2[k + 3] * f;
                }
            }
        }
        __syncthreads();

        float acc[4][4];
#pragma unroll
        for (int a = 0; a < 4; a++)
#pragma unroll
            for (int b = 0; b < 4; b++) acc[a][b] = 0.f;

#pragma unroll 8
        for (int k = 0; k < 2 * ND; k++) {
            float4 av = *reinterpret_cast<const float4*>(&sIn[k * TILE_N + tx * 4]);
            float4 bv = *reinterpret_cast<const float4*>(&sWu[k * HID + ty * 4]);
            FMA16(acc, av, bv)
        }

#pragma unroll
        for (int ei = 0; ei < 4; ei++) {
            const int n = n0 + tx * 4 + ei;
            if (n < N) {
                float4 o;
                float r;
                r = acc[ei][0] + sBu[ty * 4 + 0];
                o.x = sIn[(ty * 4 + 0) * TILE_N + tx * 4 + ei] + (r > 0.f ? r : 0.f);
                r = acc[ei][1] + sBu[ty * 4 + 1];
                o.y = sIn[(ty * 4 + 1) * TILE_N + tx * 4 + ei] + (r > 0.f ? r : 0.f);
                r = acc[ei][2] + sBu[ty * 4 + 2];
                o.z = sIn[(ty * 4 + 2) * TILE_N + tx * 4 + ei] + (r > 0.f ? r : 0.f);
                r = acc[ei][3] + sBu[ty * 4 + 3];
                o.w = sIn[(ty * 4 + 3) * TILE_N + tx * 4 + ei] + (r > 0.f ? r : 0.f);
                *reinterpret_cast<float4*>(out + (size_t)n * HID + ty * 4) = o;
            }
        }
        __syncthreads();
    }
}

// ---------------------------------------------------------------------------
extern "C" void kernel_launch(void* const* d_in, const int* in_sizes, int n_in,
                              void* d_out, int out_size) {
    const float* x   = (const float*)d_in[0];
    const int*   ei  = (const int*)d_in[1];
    const float* ea  = (const float*)d_in[2];
    const float* W1  = (const float*)d_in[3];
    const float* b1  = (const float*)d_in[4];
    const float* W2  = (const float*)d_in[5];
    const float* b2  = (const float*)d_in[6];
    const float* Wu  = (const float*)d_in[7];
    const float* bu  = (const float*)d_in[8];
    float* out = (float*)d_out;

    const int N = in_sizes[0] / ND;     // 100000
    const int E = in_sizes[2] / EDIM;   // 1600000

    const int smem_edge = (MSGIN * LDW_H + HID * LDW_H + 16 * 32 * LDIN_H) * 2 +
                          512 * 4;
    const int smem_node = (2 * ND * HID + 2 * ND * TILE_N + 2 * HID) * 4;

    cudaFuncSetAttribute(edge_kernel, cudaFuncAttributeMaxDynamicSharedMemorySize,
                         smem_edge);
    cudaFuncSetAttribute(node_kernel, cudaFuncAttributeMaxDynamicSharedMemorySize,
                         smem_node);

    const int nwt = (E + 31) / 32;
    const int ntiles = (N + TILE_N - 1) / TILE_N;

    zero_kernel<<<2048, 256>>>(N);
    convx_kernel<<<1024, 256>>>(x, N);
    edge_kernel<<<148, 512, smem_edge>>>(ei, ea, W1, b1, W2, E, nwt);
    node_kernel<<<456, 256, smem_node>>>(x, Wu, bu, b2, out, N, ntiles);
}

// round 7
// speedup vs baseline: 1.6117x; 1.1672x over previous
#include <cuda_runtime.h>
#include <cuda_bf16.h>
#include <cstdint>

// EdgeConv: message MLP over edges + mean-aggregate + update MLP + residual.
// R7: R6 + cp.async double-buffered gather (2 stages x 16 rows per warp),
// index prefetch one tile ahead, edge_attr staged raw f32 in row padding.

#define ND      64
#define EDIM    16
#define HID     64
#define MSGIN   144   // 2*ND + EDIM
#define TILE_N  64
#define MAXN    100000

#define LDIN_H  184   // bf16 In row stride (368B): ldsm offsets distinct mod-32
#define LDW_H   88    // bf16 weight row stride (176B)
#define LDSC_F  92    // f32 view of In row stride

// Scratch (device globals: no allocation allowed)
__device__ float         g_agg[(size_t)MAXN * HID];
__device__ float         g_cnt[MAXN];
__device__ __nv_bfloat16 g_xh[(size_t)MAXN * ND];

static __device__ __forceinline__ uint32_t s2u(const void* p) {
    return (uint32_t)__cvta_generic_to_shared(p);
}

static __device__ __forceinline__ void cp16(uint32_t dst, const void* src) {
    asm volatile("cp.async.cg.shared.global [%0], [%1], 16;" :: "r"(dst), "l"(src));
}

static __device__ __forceinline__ void ldsm_x4(uint32_t addr, uint32_t& r0,
                                               uint32_t& r1, uint32_t& r2,
                                               uint32_t& r3) {
    asm volatile("ldmatrix.sync.aligned.m8n8.x4.shared.b16 {%0,%1,%2,%3}, [%4];"
                 : "=r"(r0), "=r"(r1), "=r"(r2), "=r"(r3) : "r"(addr));
}

static __device__ __forceinline__ void ldsm_x4t(uint32_t addr, uint32_t& r0,
                                                uint32_t& r1, uint32_t& r2,
                                                uint32_t& r3) {
    asm volatile("ldmatrix.sync.aligned.m8n8.x4.trans.shared.b16 {%0,%1,%2,%3}, [%4];"
                 : "=r"(r0), "=r"(r1), "=r"(r2), "=r"(r3) : "r"(addr));
}

static __device__ __forceinline__ void mma16816(float* c, uint32_t a0, uint32_t a1,
                                                uint32_t a2, uint32_t a3,
                                                uint32_t b0, uint32_t b1) {
    asm volatile(
        "mma.sync.aligned.m16n8k16.row.col.f32.bf16.bf16.f32 "
        "{%0,%1,%2,%3}, {%4,%5,%6,%7}, {%8,%9}, {%0,%1,%2,%3};"
        : "+f"(c[0]), "+f"(c[1]), "+f"(c[2]), "+f"(c[3])
        : "r"(a0), "r"(a1), "r"(a2), "r"(a3), "r"(b0), "r"(b1));
}

static __device__ __forceinline__ uint32_t cvt2(float lo, float hi) {
    __nv_bfloat162 p = __floats2bfloat162_rn(lo, hi);
    return *reinterpret_cast<uint32_t*>(&p);
}

// ---------------------------------------------------------------------------
__global__ void zero_kernel(int N) {
    long long i = (long long)blockIdx.x * blockDim.x + threadIdx.x;
    long long stride = (long long)gridDim.x * blockDim.x;
    float4* a4 = reinterpret_cast<float4*>(g_agg);
    long long n4 = (long long)N * (HID / 4);
    float4 z = make_float4(0.f, 0.f, 0.f, 0.f);
    for (long long j = i; j < n4; j += stride) a4[j] = z;
    for (long long j = i; j < N; j += stride) g_cnt[j] = 0.f;
}

__global__ void convx_kernel(const float* __restrict__ x, int N) {
    int i = blockIdx.x * blockDim.x + threadIdx.x;
    int stride = gridDim.x * blockDim.x;
    const int n8 = N * ND / 8;
    const float4* xin = reinterpret_cast<const float4*>(x);
    uint4* xo = reinterpret_cast<uint4*>(g_xh);
    for (int j = i; j < n8; j += stride) {
        float4 a = xin[2 * j], b = xin[2 * j + 1];
        uint4 u;
        u.x = cvt2(a.x, a.y); u.y = cvt2(a.z, a.w);
        u.z = cvt2(b.x, b.y); u.w = cvt2(b.z, b.w);
        xo[j] = u;
    }
}

// ---------------------------------------------------------------------------
// Issue cp.asyncs for one 16-edge tile into stage {0,1} of this warp's buffer.
// Row layout (bytes): [0,128) xs bf16 | [128,256) xd bf16 | [256,288) ea bf16
// (written at compute time) | [288,352) ea f32 staging | [352,368) pad.
// ---------------------------------------------------------------------------
static __device__ __forceinline__ void issue_stage(
    __nv_bfloat16* myIn, uint32_t inU32, int* myDst, int stage, int tile,
    int myIdx, const float* __restrict__ ea, int E, int lane) {
    const int el = lane >> 1;
    const int part = lane & 1;
    const int e = tile * 16 + el;
    const uint32_t rb = inU32 + (uint32_t)(stage * 16 + el) * (LDIN_H * 2);
    if (e < E) {
        const char* ap = reinterpret_cast<const char*>(ea + (size_t)e * EDIM);
        if (part == 0) {
            const char* xs = reinterpret_cast<const char*>(g_xh + (size_t)myIdx * ND);
#pragma unroll
            for (int i = 0; i < 8; i++) cp16(rb + i * 16, xs + i * 16);
            cp16(rb + 288, ap);
            cp16(rb + 304, ap + 16);
        } else {
            myDst[stage * 16 + el] = myIdx;
            const char* xd = reinterpret_cast<const char*>(g_xh + (size_t)myIdx * ND);
#pragma unroll
            for (int i = 0; i < 8; i++) cp16(rb + 128 + i * 16, xd + i * 16);
            cp16(rb + 320, ap + 32);
            cp16(rb + 336, ap + 48);
        }
    } else {
        uint4 z = make_uint4(0, 0, 0, 0);
        uint4* rp4 = reinterpret_cast<uint4*>(myIn + (stage * 16 + el) * LDIN_H);
        if (part == 0) {
#pragma unroll
            for (int i = 0; i < 8; i++) rp4[i] = z;
            rp4[18] = z; rp4[19] = z;
        } else {
            myDst[stage * 16 + el] = -1;
#pragma unroll
            for (int i = 0; i < 8; i++) rp4[8 + i] = z;
            rp4[20] = z; rp4[21] = z;
        }
    }
}

// ---------------------------------------------------------------------------
// Edge kernel: 512 threads, 16 warps, 1 CTA/SM. Each warp processes 16-edge
// tiles with a 2-stage cp.async pipeline.
// ---------------------------------------------------------------------------
__global__ void __launch_bounds__(512, 1)
edge_kernel(const int* __restrict__ eidx, const float* __restrict__ ea,
            const float* __restrict__ W1, const float* __restrict__ b1,
            const float* __restrict__ W2, int E, int nst) {
    extern __shared__ __align__(16) char smraw[];
    __nv_bfloat16* sW1h = reinterpret_cast<__nv_bfloat16*>(smraw);      // 144*88
    __nv_bfloat16* sW2h = sW1h + MSGIN * LDW_H;                         // 64*88
    __nv_bfloat16* sIn  = sW2h + HID * LDW_H;                           // 16w*32*184
    int*           sDst = reinterpret_cast<int*>(sIn + 16 * 32 * LDIN_H); // 512

    const int tid = threadIdx.x;
    for (int i = tid; i < MSGIN * HID; i += 512) {
        int k = i >> 6, n = i & 63;
        sW1h[k * LDW_H + n] = __float2bfloat16_rn(W1[i]);
    }
    for (int i = tid; i < HID * HID; i += 512) {
        int k = i >> 6, n = i & 63;
        sW2h[k * LDW_H + n] = __float2bfloat16_rn(W2[i]);
    }
    __syncthreads();

    const int wid  = tid >> 5;
    const int lane = tid & 31;
    const int gq   = lane >> 2;       // fragment row group
    const int tq   = lane & 3;        // fragment col group
    const int el   = lane >> 1;       // gather edge slot
    const int part = lane & 1;        // gather half
    const int gw   = blockIdx.x * 16 + wid;
    const int gstride = gridDim.x * 16;

    const int* __restrict__ srcp = eidx;
    const int* __restrict__ dstp = eidx + E;
    const int* __restrict__ idxp = part ? dstp : srcp;

    __nv_bfloat16* myIn  = sIn + wid * 32 * LDIN_H;
    float*         myScr = reinterpret_cast<float*>(myIn);
    int*           myDst = sDst + wid * 32;
    const uint32_t inU32 = s2u(myIn);

    // per-lane b1 bias pairs: ntile j covers cols 8j+2tq, 8j+2tq+1
    float2 bias1[8];
#pragma unroll
    for (int j = 0; j < 8; j++) {
        bias1[j].x = b1[8 * j + 2 * tq];
        bias1[j].y = b1[8 * j + 2 * tq + 1];
    }

    // ldmatrix lane-address bases (bytes)
    const uint32_t inBase = inU32 + (((lane & 15) * LDIN_H) + 8 * (lane >> 4)) * 2;
    const uint32_t w1Base = s2u(sW1h) + (((lane & 15) * LDW_H) + 8 * (lane >> 4)) * 2;
    const uint32_t w2Base = s2u(sW2h) + (((lane & 15) * LDW_H) + 8 * (lane >> 4)) * 2;

    // ---- prologue: issue tile gw into stage 0; prefetch idx for gw+g ----
    {
        int e0 = gw * 16 + el;
        int idx0 = (e0 < E) ? idxp[e0] : 0;
        issue_stage(myIn, inU32, myDst, 0, gw, idx0, ea, E, lane);
    }
    asm volatile("cp.async.commit_group;" ::: "memory");
    int idxN = 0;
    {
        int tn = gw + gstride;
        int en = tn * 16 + el;
        if (tn < nst && en < E) idxN = idxp[en];
    }

    int it = 0;
    for (int t = gw; t < nst; t += gstride, it++) {
        const int s = it & 1;
        const int r0 = s * 16;
        const int tnext = t + gstride;

        // issue next tile into the other stage; commit; prefetch idx t+2g
        if (tnext < nst)
            issue_stage(myIn, inU32, myDst, s ^ 1, tnext, idxN, ea, E, lane);
        asm volatile("cp.async.commit_group;" ::: "memory");
        {
            const int t2 = tnext + gstride;
            const int e2 = t2 * 16 + el;
            idxN = (t2 < nst && e2 < E) ? idxp[e2] : 0;
        }

        // wait for tile t's group (newest group may stay in flight)
        asm volatile("cp.async.wait_group 1;" ::: "memory");
        __syncwarp();

        // ---- convert staged ea f32 -> bf16 cols 128..143 ----
        {
            float* rowf = myScr + (r0 + el) * LDSC_F;
            float4 a = *reinterpret_cast<const float4*>(rowf + 72 + part * 8);
            float4 b = *reinterpret_cast<const float4*>(rowf + 76 + part * 8);
            uint4 u;
            u.x = cvt2(a.x, a.y); u.y = cvt2(a.z, a.w);
            u.z = cvt2(b.x, b.y); u.w = cvt2(b.z, b.w);
            *reinterpret_cast<uint4*>(reinterpret_cast<char*>(rowf) + 256 + part * 16) = u;
        }
        __syncwarp();

        // ---- GEMM1: (16 x 144) @ (144 x 64) ----
        float acc[8][4];
#pragma unroll
        for (int j = 0; j < 8; j++)
#pragma unroll
            for (int q = 0; q < 4; q++) acc[j][q] = 0.f;

        const uint32_t inH = inBase + r0 * LDIN_H * 2;
#pragma unroll
        for (int k = 0; k < MSGIN / 16; k++) {
            uint32_t a0, a1, a2, a3;
            ldsm_x4(inH + k * 32, a0, a1, a2, a3);
#pragma unroll
            for (int nb = 0; nb < 4; nb++) {
                uint32_t p0, p1, p2, p3;
                ldsm_x4t(w1Base + (k * 16 * LDW_H + nb * 16) * 2, p0, p1, p2, p3);
                mma16816(acc[2 * nb],     a0, a1, a2, a3, p0, p1);
                mma16816(acc[2 * nb + 1], a0, a1, a2, a3, p2, p3);
            }
        }

        // ---- bias + ReLU + cvt -> A fragments of GEMM2 (registers) ----
        uint32_t aH[16];
#pragma unroll
        for (int q = 0; q < 4; q++) {
            const int j0 = 2 * q, j1 = 2 * q + 1;
            aH[4 * q + 0] = cvt2(fmaxf(acc[j0][0] + bias1[j0].x, 0.f),
                                 fmaxf(acc[j0][1] + bias1[j0].y, 0.f));
            aH[4 * q + 1] = cvt2(fmaxf(acc[j0][2] + bias1[j0].x, 0.f),
                                 fmaxf(acc[j0][3] + bias1[j0].y, 0.f));
            aH[4 * q + 2] = cvt2(fmaxf(acc[j1][0] + bias1[j1].x, 0.f),
                                 fmaxf(acc[j1][1] + bias1[j1].y, 0.f));
            aH[4 * q + 3] = cvt2(fmaxf(acc[j1][2] + bias1[j1].x, 0.f),
                                 fmaxf(acc[j1][3] + bias1[j1].y, 0.f));
        }

        // ---- GEMM2: (16 x 64) @ (64 x 64) ----
#pragma unroll
        for (int j = 0; j < 8; j++)
#pragma unroll
            for (int q = 0; q < 4; q++) acc[j][q] = 0.f;
#pragma unroll
        for (int q = 0; q < 4; q++) {
#pragma unroll
            for (int nb = 0; nb < 4; nb++) {
                uint32_t p0, p1, p2, p3;
                ldsm_x4t(w2Base + (q * 16 * LDW_H + nb * 16) * 2, p0, p1, p2, p3);
                mma16816(acc[2 * nb],     aH[4 * q + 0], aH[4 * q + 1],
                         aH[4 * q + 2], aH[4 * q + 3], p0, p1);
                mma16816(acc[2 * nb + 1], aH[4 * q + 0], aH[4 * q + 1],
                         aH[4 * q + 2], aH[4 * q + 3], p2, p3);
            }
        }

        // ---- store messages to f32 scratch (aliases stage-s rows) ----
        {
            float* base0 = myScr + (r0 + gq) * LDSC_F + 2 * tq;
            float* base1 = myScr + (r0 + gq + 8) * LDSC_F + 2 * tq;
#pragma unroll
            for (int j = 0; j < 8; j++) {
                *reinterpret_cast<float2*>(base0 + 8 * j) =
                    make_float2(acc[j][0], acc[j][1]);
                *reinterpret_cast<float2*>(base1 + 8 * j) =
                    make_float2(acc[j][2], acc[j][3]);
            }
        }
        __syncwarp();

        // ---- float4 atomic scatter: 16 rows x 16 float4 ----
#pragma unroll
        for (int i = 0; i < 8; i++) {
            const int idx = lane + 32 * i;
            const int row = idx >> 4;
            const int c4  = idx & 15;
            const int d = myDst[r0 + row];
            if (d >= 0) {
                float4 v = *reinterpret_cast<const float4*>(
                    myScr + (r0 + row) * LDSC_F + c4 * 4);
                atomicAdd(reinterpret_cast<float4*>(
                    g_agg + (size_t)d * HID + c4 * 4), v);
            }
        }
        if (lane < 16) {
            const int d = myDst[r0 + lane];
            if (d >= 0) atomicAdd(&g_cnt[d], 1.0f);
        }
        __syncwarp();
    }
}

// ---------------------------------------------------------------------------
// Node kernel: fp32 exact; mean + b2 folded into aggregate load.
// ---------------------------------------------------------------------------
#define FMA16(ACC, AV, BV)                                                    \
  ACC[0][0] = fmaf(AV.x, BV.x, ACC[0][0]);                                    \
  ACC[0][1] = fmaf(AV.x, BV.y, ACC[0][1]);                                    \
  ACC[0][2] = fmaf(AV.x, BV.z, ACC[0][2]);                                    \
  ACC[0][3] = fmaf(AV.x, BV.w, ACC[0][3]);                                    \
  ACC[1][0] = fmaf(AV.y, BV.x, ACC[1][0]);                                    \
  ACC[1][1] = fmaf(AV.y, BV.y, ACC[1][1]);                                    \
  ACC[1][2] = fmaf(AV.y, BV.z, ACC[1][2]);                                    \
  ACC[1][3] = fmaf(AV.y, BV.w, ACC[1][3]);                                    \
  ACC[2][0] = fmaf(AV.z, BV.x, ACC[2][0]);                                    \
  ACC[2][1] = fmaf(AV.z, BV.y, ACC[2][1]);                                    \
  ACC[2][2] = fmaf(AV.z, BV.z, ACC[2][2]);                                    \
  ACC[2][3] = fmaf(AV.z, BV.w, ACC[2][3]);                                    \
  ACC[3][0] = fmaf(AV.w, BV.x, ACC[3][0]);                                    \
  ACC[3][1] = fmaf(AV.w, BV.y, ACC[3][1]);                                    \
  ACC[3][2] = fmaf(AV.w, BV.z, ACC[3][2]);                                    \
  ACC[3][3] = fmaf(AV.w, BV.w, ACC[3][3]);

__global__ void __launch_bounds__(256, 3)
node_kernel(const float* __restrict__ x, const float* __restrict__ Wu,
            const float* __restrict__ bu, const float* __restrict__ b2,
            float* __restrict__ out, int N, int ntiles) {
    extern __shared__ float smn[];
    float* sWu = smn;                     // [128][64]
    float* sIn = sWu + 2 * ND * HID;      // [128][64]
    float* sBu = sIn + 2 * ND * TILE_N;   // [64]
    float* sB2 = sBu + HID;               // [64]

    const int tid = threadIdx.x;
    for (int i = tid; i < 2 * ND * HID; i += 256) sWu[i] = Wu[i];
    if (tid < HID) { sBu[tid] = bu[tid]; sB2[tid] = b2[tid]; }
    __syncthreads();

    const int tx = tid & 15;
    const int ty = tid >> 4;
    const int q  = tid & 3;
    const int ng = tid >> 2;

    for (int tile = blockIdx.x; tile < ntiles; tile += gridDim.x) {
        const int n0 = tile * TILE_N;
        {
            const int n = n0 + ng;
            if (n < N) {
                const float cnt = g_cnt[n];
                const float inv = 1.0f / (cnt + 1e-6f);
                const float f   = cnt * inv;
                const float4* xr = reinterpret_cast<const float4*>(x + (size_t)n * ND);
                const float4* ar = reinterpret_cast<const float4*>(g_agg + (size_t)n * HID);
#pragma unroll
                for (int i = 0; i < 4; i++) {
                    const int f4 = q + 4 * i;
                    const int k  = f4 * 4;
                    float4 v = xr[f4];
                    sIn[(k + 0) * TILE_N + ng] = v.x;
                    sIn[(k + 1) * TILE_N + ng] = v.y;
                    sIn[(k + 2) * TILE_N + ng] = v.z;
                    sIn[(k + 3) * TILE_N + ng] = v.w;
                    float4 w = ar[f4];
                    sIn[(ND + k + 0) * TILE_N + ng] = w.x * inv + sB2[k + 0] * f;
                    sIn[(ND + k + 1) * TILE_N + ng] = w.y * inv + sB2[k + 1] * f;
                    sIn[(ND + k + 2) * TILE_N + ng] = w.z * inv + sB2[k + 2] * f;
                    sIn[(ND + k + 3) * TILE_N + ng] = w.w * inv + sB2[k + 3] * f;
                }
            }
        }
        __syncthreads();

        float acc[4][4];
#pragma unroll
        for (int a = 0; a < 4; a++)
#pragma unroll
            for (int b = 0; b < 4; b++) acc[a][b] = 0.f;

#pragma unroll 8
        for (int k = 0; k < 2 * ND; k++) {
            float4 av = *reinterpret_cast<const float4*>(&sIn[k * TILE_N + tx * 4]);
            float4 bv = *reinterpret_cast<const float4*>(&sWu[k * HID + ty * 4]);
            FMA16(acc, av, bv)
        }

#pragma unroll
        for (int ei = 0; ei < 4; ei++) {
            const int n = n0 + tx * 4 + ei;
            if (n < N) {
                float4 o;
                float r;
                r = acc[ei][0] + sBu[ty * 4 + 0];
                o.x = sIn[(ty * 4 + 0) * TILE_N + tx * 4 + ei] + (r > 0.f ? r : 0.f);
                r = acc[ei][1] + sBu[ty * 4 + 1];
                o.y = sIn[(ty * 4 + 1) * TILE_N + tx * 4 + ei] + (r > 0.f ? r : 0.f);
                r = acc[ei][2] + sBu[ty * 4 + 2];
                o.z = sIn[(ty * 4 + 2) * TILE_N + tx * 4 + ei] + (r > 0.f ? r : 0.f);
                r = acc[ei][3] + sBu[ty * 4 + 3];
                o.w = sIn[(ty * 4 + 3) * TILE_N + tx * 4 + ei] + (r > 0.f ? r : 0.f);
                *reinterpret_cast<float4*>(out + (size_t)n * HID + ty * 4) = o;
            }
        }
        __syncthreads();
    }
}

// ---------------------------------------------------------------------------
extern "C" void kernel_launch(void* const* d_in, const int* in_sizes, int n_in,
                              void* d_out, int out_size) {
    const float* x   = (const float*)d_in[0];
    const int*   ei  = (const int*)d_in[1];
    const float* ea  = (const float*)d_in[2];
    const float* W1  = (const float*)d_in[3];
    const float* b1  = (const float*)d_in[4];
    const float* W2  = (const float*)d_in[5];
    const float* b2  = (const float*)d_in[6];
    const float* Wu  = (const float*)d_in[7];
    const float* bu  = (const float*)d_in[8];
    float* out = (float*)d_out;

    const int N = in_sizes[0] / ND;     // 100000
    const int E = in_sizes[2] / EDIM;   // 1600000

    const int smem_edge = (MSGIN * LDW_H + HID * LDW_H + 16 * 32 * LDIN_H) * 2 +
                          512 * 4;      // 227072 B
    const int smem_node = (2 * ND * HID + 2 * ND * TILE_N + 2 * HID) * 4;

    cudaFuncSetAttribute(edge_kernel, cudaFuncAttributeMaxDynamicSharedMemorySize,
                         smem_edge);
    cudaFuncSetAttribute(node_kernel, cudaFuncAttributeMaxDynamicSharedMemorySize,
                         smem_node);

    const int nst = (E + 15) / 16;      // 16-edge stage tiles
    const int ntiles = (N + TILE_N - 1) / TILE_N;

    zero_kernel<<<2048, 256>>>(N);
    convx_kernel<<<1024, 256>>>(x, N);
    edge_kernel<<<148, 512, smem_edge>>>(ei, ea, W1, b1, W2, E, nst);
    node_kernel<<<456, 256, smem_node>>>(x, Wu, bu, b2, out, N, ntiles);
}

// round 9
// speedup vs baseline: 1.6312x; 1.0121x over previous
#include <cuda_runtime.h>
#include <cuda_bf16.h>
#include <cstdint>

// EdgeConv: message MLP over edges + mean-aggregate + update MLP + residual.
// R9: factor GEMM1 = [xs|xd|ea]@W1 into per-node precompute P=x@W1a, Q=x@W1b
// (dense, done once) + per-edge ea@W1c (K=16 MMA) + scalar adds. Edge MMA work
// drops 13 k-steps -> 5. tcgen05 unavailable (harness targets sm_103, not
// sm_103a), so this attacks the legacy-HMMA FLOP budget instead.

#define ND      64
#define EDIM    16
#define HID     64
#define MSGIN   144
#define TILE_N  64
#define MAXN    100000

#define LDIN_H  184   // bf16 In row stride (368B): conflict-free (92w ≡ 28 mod 32)
#define LDW_H   88    // bf16 weight row stride (176B)
#define LDX_H   72    // pq kernel x-tile row stride (144B, 36w ≡ 4 mod 32)
#define LDSC_F  92    // f32 view of In row stride

// Row layout (bf16 elements): [0,16) ea | [16,80) P[src] | [80,144) Q[dst]
// | [144,176) ea f32 staging (8 f32/part) | [176,184) pad.

__device__ float         g_agg[(size_t)MAXN * HID];
__device__ float         g_cnt[MAXN];
__device__ __nv_bfloat16 g_P[(size_t)MAXN * HID];
__device__ __nv_bfloat16 g_Q[(size_t)MAXN * HID];

static __device__ __forceinline__ uint32_t s2u(const void* p) {
    return (uint32_t)__cvta_generic_to_shared(p);
}
static __device__ __forceinline__ void cp16(uint32_t dst, const void* src) {
    asm volatile("cp.async.cg.shared.global [%0], [%1], 16;" :: "r"(dst), "l"(src));
}
static __device__ __forceinline__ void ldsm_x4(uint32_t addr, uint32_t& r0,
                                               uint32_t& r1, uint32_t& r2,
                                               uint32_t& r3) {
    asm volatile("ldmatrix.sync.aligned.m8n8.x4.shared.b16 {%0,%1,%2,%3}, [%4];"
                 : "=r"(r0), "=r"(r1), "=r"(r2), "=r"(r3) : "r"(addr));
}
static __device__ __forceinline__ void ldsm_x4t(uint32_t addr, uint32_t& r0,
                                                uint32_t& r1, uint32_t& r2,
                                                uint32_t& r3) {
    asm volatile("ldmatrix.sync.aligned.m8n8.x4.trans.shared.b16 {%0,%1,%2,%3}, [%4];"
                 : "=r"(r0), "=r"(r1), "=r"(r2), "=r"(r3) : "r"(addr));
}
static __device__ __forceinline__ void mma16816(float* c, uint32_t a0, uint32_t a1,
                                                uint32_t a2, uint32_t a3,
                                                uint32_t b0, uint32_t b1) {
    asm volatile(
        "mma.sync.aligned.m16n8k16.row.col.f32.bf16.bf16.f32 "
        "{%0,%1,%2,%3}, {%4,%5,%6,%7}, {%8,%9}, {%0,%1,%2,%3};"
        : "+f"(c[0]), "+f"(c[1]), "+f"(c[2]), "+f"(c[3])
        : "r"(a0), "r"(a1), "r"(a2), "r"(a3), "r"(b0), "r"(b1));
}
static __device__ __forceinline__ uint32_t cvt2(float lo, float hi) {
    __nv_bfloat162 p = __floats2bfloat162_rn(lo, hi);
    return *reinterpret_cast<uint32_t*>(&p);
}

// ---------------------------------------------------------------------------
__global__ void zero_kernel(int N) {
    long long i = (long long)blockIdx.x * blockDim.x + threadIdx.x;
    long long stride = (long long)gridDim.x * blockDim.x;
    float4* a4 = reinterpret_cast<float4*>(g_agg);
    long long n4 = (long long)N * (HID / 4);
    float4 z = make_float4(0.f, 0.f, 0.f, 0.f);
    for (long long j = i; j < n4; j += stride) a4[j] = z;
    for (long long j = i; j < N; j += stride) g_cnt[j] = 0.f;
}

// ---------------------------------------------------------------------------
// pq_kernel: P = x @ W1[0:64], Q = x @ W1[64:128], bf16 outputs.
// 256 thr = 8 warps; each warp owns 16-node tiles.
// ---------------------------------------------------------------------------
__global__ void __launch_bounds__(256)
pq_kernel(const float* __restrict__ x, const float* __restrict__ W1,
          int N, int ntiles) {
    extern __shared__ __align__(16) char smq[];
    __nv_bfloat16* sWa = reinterpret_cast<__nv_bfloat16*>(smq);   // 64*88
    __nv_bfloat16* sWb = sWa + 64 * LDW_H;                         // 64*88
    __nv_bfloat16* sX  = sWb + 64 * LDW_H;                         // 8*16*72

    const int tid = threadIdx.x;
    for (int i = tid; i < 64 * 64; i += 256) {
        int k = i >> 6, n = i & 63;
        sWa[k * LDW_H + n] = __float2bfloat16_rn(W1[k * HID + n]);
        sWb[k * LDW_H + n] = __float2bfloat16_rn(W1[(64 + k) * HID + n]);
    }
    __syncthreads();

    const int wid = tid >> 5, lane = tid & 31;
    const int gq = lane >> 2, tq = lane & 3;
    const int el = lane >> 1, part = lane & 1;

    __nv_bfloat16* myX = sX + wid * 16 * LDX_H;
    const uint32_t xBase = s2u(myX) + (((lane & 15) * LDX_H) + 8 * (lane >> 4)) * 2;
    const uint32_t waBase = s2u(sWa) + (((lane & 15) * LDW_H) + 8 * (lane >> 4)) * 2;
    const uint32_t wbBase = s2u(sWb) + (((lane & 15) * LDW_H) + 8 * (lane >> 4)) * 2;

    for (int t = blockIdx.x * 8 + wid; t < ntiles; t += gridDim.x * 8) {
        const int n0 = t * 16;
        // gather: 2 lanes per node, f32 -> bf16
        {
            const int n = n0 + el;
            uint4* dst = reinterpret_cast<uint4*>(myX + el * LDX_H + part * 32);
            if (n < N) {
                const float4* xr = reinterpret_cast<const float4*>(
                    x + (size_t)n * ND) + part * 8;
#pragma unroll
                for (int i = 0; i < 4; i++) {
                    float4 a = xr[2 * i], b = xr[2 * i + 1];
                    uint4 u;
                    u.x = cvt2(a.x, a.y); u.y = cvt2(a.z, a.w);
                    u.z = cvt2(b.x, b.y); u.w = cvt2(b.z, b.w);
                    dst[i] = u;
                }
            } else {
                uint4 z = make_uint4(0, 0, 0, 0);
#pragma unroll
                for (int i = 0; i < 4; i++) dst[i] = z;
            }
        }
        __syncwarp();

        float accP[8][4], accQ[8][4];
#pragma unroll
        for (int j = 0; j < 8; j++)
#pragma unroll
            for (int q = 0; q < 4; q++) { accP[j][q] = 0.f; accQ[j][q] = 0.f; }

#pragma unroll
        for (int k = 0; k < 4; k++) {
            uint32_t a0, a1, a2, a3;
            ldsm_x4(xBase + k * 32, a0, a1, a2, a3);
#pragma unroll
            for (int nb = 0; nb < 4; nb++) {
                uint32_t p0, p1, p2, p3;
                ldsm_x4t(waBase + (k * 16 * LDW_H + nb * 16) * 2, p0, p1, p2, p3);
                mma16816(accP[2 * nb],     a0, a1, a2, a3, p0, p1);
                mma16816(accP[2 * nb + 1], a0, a1, a2, a3, p2, p3);
                ldsm_x4t(wbBase + (k * 16 * LDW_H + nb * 16) * 2, p0, p1, p2, p3);
                mma16816(accQ[2 * nb],     a0, a1, a2, a3, p0, p1);
                mma16816(accQ[2 * nb + 1], a0, a1, a2, a3, p2, p3);
            }
        }

        const int r0n = n0 + gq, r1n = n0 + gq + 8;
#pragma unroll
        for (int j = 0; j < 8; j++) {
            const int c = 8 * j + 2 * tq;
            if (r0n < N) {
                *reinterpret_cast<uint32_t*>(g_P + (size_t)r0n * HID + c) =
                    cvt2(accP[j][0], accP[j][1]);
                *reinterpret_cast<uint32_t*>(g_Q + (size_t)r0n * HID + c) =
                    cvt2(accQ[j][0], accQ[j][1]);
            }
            if (r1n < N) {
                *reinterpret_cast<uint32_t*>(g_P + (size_t)r1n * HID + c) =
                    cvt2(accP[j][2], accP[j][3]);
                *reinterpret_cast<uint32_t*>(g_Q + (size_t)r1n * HID + c) =
                    cvt2(accQ[j][2], accQ[j][3]);
            }
        }
        __syncwarp();
    }
}

// ---------------------------------------------------------------------------
// Gather one 16-edge tile stage: P[src] -> [16,80), Q[dst] -> [80,144),
// ea f32 -> staging [144,176).
// ---------------------------------------------------------------------------
static __device__ __forceinline__ void issue_stage(
    __nv_bfloat16* myIn, uint32_t inU32, int* myDst, int stage, int tile,
    int myIdx, const float* __restrict__ ea, int E, int lane) {
    const int el = lane >> 1;
    const int part = lane & 1;
    const int e = tile * 16 + el;
    const uint32_t rb = inU32 + (uint32_t)(stage * 16 + el) * (LDIN_H * 2);
    if (e < E) {
        const char* ap = reinterpret_cast<const char*>(ea + (size_t)e * EDIM);
        if (part == 0) {
            const char* ps = reinterpret_cast<const char*>(g_P + (size_t)myIdx * HID);
#pragma unroll
            for (int i = 0; i < 8; i++) cp16(rb + 32 + i * 16, ps + i * 16);
            cp16(rb + 288, ap);
            cp16(rb + 304, ap + 16);
        } else {
            myDst[stage * 16 + el] = myIdx;
            const char* qd = reinterpret_cast<const char*>(g_Q + (size_t)myIdx * HID);
#pragma unroll
            for (int i = 0; i < 8; i++) cp16(rb + 160 + i * 16, qd + i * 16);
            cp16(rb + 320, ap + 32);
            cp16(rb + 336, ap + 48);
        }
    } else {
        uint4 z = make_uint4(0, 0, 0, 0);
        uint4* rp4 = reinterpret_cast<uint4*>(myIn + (stage * 16 + el) * LDIN_H);
        if (part == 0) {
#pragma unroll
            for (int i = 2; i < 10; i++) rp4[i] = z;   // P
            rp4[18] = z; rp4[19] = z;                  // ea stage lo
        } else {
            myDst[stage * 16 + el] = -1;
#pragma unroll
            for (int i = 10; i < 18; i++) rp4[i] = z;  // Q
            rp4[20] = z; rp4[21] = z;                  // ea stage hi
        }
    }
}

// ---------------------------------------------------------------------------
// Edge kernel: 512 threads, 16 warps, 1 CTA/SM. 2-stage cp.async pipeline.
// GEMM1 = ea(16x16) @ W1c(16x64); epilogue adds P+Q+b1, ReLU, cvt -> GEMM2.
// ---------------------------------------------------------------------------
__global__ void __launch_bounds__(512, 1)
edge_kernel(const int* __restrict__ eidx, const float* __restrict__ ea,
            const float* __restrict__ W1, const float* __restrict__ b1,
            const float* __restrict__ W2, int E, int nst) {
    extern __shared__ __align__(16) char smraw[];
    __nv_bfloat16* sW1c = reinterpret_cast<__nv_bfloat16*>(smraw);      // 16*88
    __nv_bfloat16* sW2h = sW1c + 16 * LDW_H;                            // 64*88
    __nv_bfloat16* sIn  = sW2h + HID * LDW_H;                           // 16w*32*184
    int*           sDst = reinterpret_cast<int*>(sIn + 16 * 32 * LDIN_H); // 512

    const int tid = threadIdx.x;
    for (int i = tid; i < 16 * HID; i += 512) {
        int k = i >> 6, n = i & 63;
        sW1c[k * LDW_H + n] = __float2bfloat16_rn(W1[(128 + k) * HID + n]);
    }
    for (int i = tid; i < HID * HID; i += 512) {
        int k = i >> 6, n = i & 63;
        sW2h[k * LDW_H + n] = __float2bfloat16_rn(W2[k * HID + n]);
    }
    __syncthreads();

    const int wid  = tid >> 5;
    const int lane = tid & 31;
    const int gq   = lane >> 2;       // fragment row group
    const int tq   = lane & 3;        // fragment col group
    const int el   = lane >> 1;       // gather edge slot
    const int part = lane & 1;        // gather half
    const int gw   = blockIdx.x * 16 + wid;
    const int gstride = gridDim.x * 16;

    const int* __restrict__ srcp = eidx;
    const int* __restrict__ dstp = eidx + E;
    const int* __restrict__ idxp = part ? dstp : srcp;

    __nv_bfloat16* myIn  = sIn + wid * 32 * LDIN_H;
    float*         myScr = reinterpret_cast<float*>(myIn);
    int*           myDst = sDst + wid * 32;
    const uint32_t inU32 = s2u(myIn);

    float2 bias1[8];
#pragma unroll
    for (int j = 0; j < 8; j++) {
        bias1[j].x = b1[8 * j + 2 * tq];
        bias1[j].y = b1[8 * j + 2 * tq + 1];
    }

    const uint32_t inBase  = inU32 + (((lane & 15) * LDIN_H) + 8 * (lane >> 4)) * 2;
    const uint32_t w1cBase = s2u(sW1c) + (((lane & 15) * LDW_H) + 8 * (lane >> 4)) * 2;
    const uint32_t w2Base  = s2u(sW2h) + (((lane & 15) * LDW_H) + 8 * (lane >> 4)) * 2;

    // ---- prologue ----
    {
        int e0 = gw * 16 + el;
        int idx0 = (e0 < E) ? idxp[e0] : 0;
        issue_stage(myIn, inU32, myDst, 0, gw, idx0, ea, E, lane);
    }
    asm volatile("cp.async.commit_group;" ::: "memory");
    int idxN = 0;
    {
        int tn = gw + gstride;
        int en = tn * 16 + el;
        if (tn < nst && en < E) idxN = idxp[en];
    }

    int it = 0;
    for (int t = gw; t < nst; t += gstride, it++) {
        const int s = it & 1;
        const int r0 = s * 16;
        const int tnext = t + gstride;

        if (tnext < nst)
            issue_stage(myIn, inU32, myDst, s ^ 1, tnext, idxN, ea, E, lane);
        asm volatile("cp.async.commit_group;" ::: "memory");
        {
            const int t2 = tnext + gstride;
            const int e2 = t2 * 16 + el;
            idxN = (t2 < nst && e2 < E) ? idxp[e2] : 0;
        }
        asm volatile("cp.async.wait_group 1;" ::: "memory");
        __syncwarp();

        // ---- convert staged ea f32 -> bf16 cols [0,16) ----
        {
            float* rowf = myScr + (r0 + el) * LDSC_F;
            float4 a = *reinterpret_cast<const float4*>(rowf + 72 + part * 8);
            float4 b = *reinterpret_cast<const float4*>(rowf + 76 + part * 8);
            uint4 u;
            u.x = cvt2(a.x, a.y); u.y = cvt2(a.z, a.w);
            u.z = cvt2(b.x, b.y); u.w = cvt2(b.z, b.w);
            *reinterpret_cast<uint4*>(reinterpret_cast<char*>(rowf) + part * 16) = u;
        }
        __syncwarp();

        // ---- GEMM1: ea(16x16) @ W1c(16x64) ----
        float acc[8][4];
#pragma unroll
        for (int j = 0; j < 8; j++)
#pragma unroll
            for (int q = 0; q < 4; q++) acc[j][q] = 0.f;
        {
            uint32_t a0, a1, a2, a3;
            ldsm_x4(inBase + r0 * LDIN_H * 2, a0, a1, a2, a3);
#pragma unroll
            for (int nb = 0; nb < 4; nb++) {
                uint32_t p0, p1, p2, p3;
                ldsm_x4t(w1cBase + (nb * 16) * 2, p0, p1, p2, p3);
                mma16816(acc[2 * nb],     a0, a1, a2, a3, p0, p1);
                mma16816(acc[2 * nb + 1], a0, a1, a2, a3, p2, p3);
            }
        }

        // ---- epilogue1: + P[src] + Q[dst] + b1, ReLU, cvt -> aH frags ----
        uint32_t aH[16];
        {
            const __nv_bfloat16* rowA = myIn + (r0 + gq) * LDIN_H + 16;      // P row gq
            const __nv_bfloat16* rowB = myIn + (r0 + gq + 8) * LDIN_H + 16;  // P row gq+8
#pragma unroll
            for (int q = 0; q < 4; q++) {
                const int j0 = 2 * q, j1 = 2 * q + 1;
                const int c0 = 8 * j0 + 2 * tq, c1 = 8 * j1 + 2 * tq;
                float2 pA0 = __bfloat1622float2(
                    *reinterpret_cast<const __nv_bfloat162*>(rowA + c0));
                float2 qA0 = __bfloat1622float2(
                    *reinterpret_cast<const __nv_bfloat162*>(rowA + 64 + c0));
                float2 pB0 = __bfloat1622float2(
                    *reinterpret_cast<const __nv_bfloat162*>(rowB + c0));
                float2 qB0 = __bfloat1622float2(
                    *reinterpret_cast<const __nv_bfloat162*>(rowB + 64 + c0));
                float2 pA1 = __bfloat1622float2(
                    *reinterpret_cast<const __nv_bfloat162*>(rowA + c1));
                float2 qA1 = __bfloat1622float2(
                    *reinterpret_cast<const __nv_bfloat162*>(rowA + 64 + c1));
                float2 pB1 = __bfloat1622float2(
                    *reinterpret_cast<const __nv_bfloat162*>(rowB + c1));
                float2 qB1 = __bfloat1622float2(
                    *reinterpret_cast<const __nv_bfloat162*>(rowB + 64 + c1));
                aH[4 * q + 0] = cvt2(
                    fmaxf(acc[j0][0] + pA0.x + qA0.x + bias1[j0].x, 0.f),
                    fmaxf(acc[j0][1] + pA0.y + qA0.y + bias1[j0].y, 0.f));
                aH[4 * q + 1] = cvt2(
                    fmaxf(acc[j0][2] + pB0.x + qB0.x + bias1[j0].x, 0.f),
                    fmaxf(acc[j0][3] + pB0.y + qB0.y + bias1[j0].y, 0.f));
                aH[4 * q + 2] = cvt2(
                    fmaxf(acc[j1][0] + pA1.x + qA1.x + bias1[j1].x, 0.f),
                    fmaxf(acc[j1][1] + pA1.y + qA1.y + bias1[j1].y, 0.f));
                aH[4 * q + 3] = cvt2(
                    fmaxf(acc[j1][2] + pB1.x + qB1.x + bias1[j1].x, 0.f),
                    fmaxf(acc[j1][3] + pB1.y + qB1.y + bias1[j1].y, 0.f));
            }
        }

        // ---- GEMM2: (16 x 64) @ (64 x 64) ----
#pragma unroll
        for (int j = 0; j < 8; j++)
#pragma unroll
            for (int q = 0; q < 4; q++) acc[j][q] = 0.f;
#pragma unroll
        for (int q = 0; q < 4; q++) {
#pragma unroll
            for (int nb = 0; nb < 4; nb++) {
                uint32_t p0, p1, p2, p3;
                ldsm_x4t(w2Base + (q * 16 * LDW_H + nb * 16) * 2, p0, p1, p2, p3);
                mma16816(acc[2 * nb],     aH[4 * q + 0], aH[4 * q + 1],
                         aH[4 * q + 2], aH[4 * q + 3], p0, p1);
                mma16816(acc[2 * nb + 1], aH[4 * q + 0], aH[4 * q + 1],
                         aH[4 * q + 2], aH[4 * q + 3], p2, p3);
            }
        }

        // ---- store messages to f32 scratch (aliases stage rows) ----
        {
            float* base0 = myScr + (r0 + gq) * LDSC_F + 2 * tq;
            float* base1 = myScr + (r0 + gq + 8) * LDSC_F + 2 * tq;
#pragma unroll
            for (int j = 0; j < 8; j++) {
                *reinterpret_cast<float2*>(base0 + 8 * j) =
                    make_float2(acc[j][0], acc[j][1]);
                *reinterpret_cast<float2*>(base1 + 8 * j) =
                    make_float2(acc[j][2], acc[j][3]);
            }
        }
        __syncwarp();

        // ---- float4 atomic scatter ----
#pragma unroll
        for (int i = 0; i < 8; i++) {
            const int idx = lane + 32 * i;
            const int row = idx >> 4;
            const int c4  = idx & 15;
            const int d = myDst[r0 + row];
            if (d >= 0) {
                float4 v = *reinterpret_cast<const float4*>(
                    myScr + (r0 + row) * LDSC_F + c4 * 4);
                atomicAdd(reinterpret_cast<float4*>(
                    g_agg + (size_t)d * HID + c4 * 4), v);
            }
        }
        if (lane < 16) {
            const int d = myDst[r0 + lane];
            if (d >= 0) atomicAdd(&g_cnt[d], 1.0f);
        }
        __syncwarp();
    }
}

// ---------------------------------------------------------------------------
// Node kernel: fp32 exact; mean + b2 folded into aggregate load. (unchanged)
// ---------------------------------------------------------------------------
#define FMA16(ACC, AV, BV)                                                    \
  ACC[0][0] = fmaf(AV.x, BV.x, ACC[0][0]);                                    \
  ACC[0][1] = fmaf(AV.x, BV.y, ACC[0][1]);                                    \
  ACC[0][2] = fmaf(AV.x, BV.z, ACC[0][2]);                                    \
  ACC[0][3] = fmaf(AV.x, BV.w, ACC[0][3]);                                    \
  ACC[1][0] = fmaf(AV.y, BV.x, ACC[1][0]);                                    \
  ACC[1][1] = fmaf(AV.y, BV.y, ACC[1][1]);                                    \
  ACC[1][2] = fmaf(AV.y, BV.z, ACC[1][2]);                                    \
  ACC[1][3] = fmaf(AV.y, BV.w, ACC[1][3]);                                    \
  ACC[2][0] = fmaf(AV.z, BV.x, ACC[2][0]);                                    \
  ACC[2][1] = fmaf(AV.z, BV.y, ACC[2][1]);                                    \
  ACC[2][2] = fmaf(AV.z, BV.z, ACC[2][2]);                                    \
  ACC[2][3] = fmaf(AV.z, BV.w, ACC[2][3]);                                    \
  ACC[3][0] = fmaf(AV.w, BV.x, ACC[3][0]);                                    \
  ACC[3][1] = fmaf(AV.w, BV.y, ACC[3][1]);                                    \
  ACC[3][2] = fmaf(AV.w, BV.z, ACC[3][2]);                                    \
  ACC[3][3] = fmaf(AV.w, BV.w, ACC[3][3]);

__global__ void __launch_bounds__(256, 3)
node_kernel(const float* __restrict__ x, const float* __restrict__ Wu,
            const float* __restrict__ bu, const float* __restrict__ b2,
            float* __restrict__ out, int N, int ntiles) {
    extern __shared__ float smn[];
    float* sWu = smn;
    float* sIn = sWu + 2 * ND * HID;
    float* sBu = sIn + 2 * ND * TILE_N;
    float* sB2 = sBu + HID;

    const int tid = threadIdx.x;
    for (int i = tid; i < 2 * ND * HID; i += 256) sWu[i] = Wu[i];
    if (tid < HID) { sBu[tid] = bu[tid]; sB2[tid] = b2[tid]; }
    __syncthreads();

    const int tx = tid & 15;
    const int ty = tid >> 4;
    const int q  = tid & 3;
    const int ng = tid >> 2;

    for (int tile = blockIdx.x; tile < ntiles; tile += gridDim.x) {
        const int n0 = tile * TILE_N;
        {
            const int n = n0 + ng;
            if (n < N) {
                const float cnt = g_cnt[n];
                const float inv = 1.0f / (cnt + 1e-6f);
                const float f   = cnt * inv;
                const float4* xr = reinterpret_cast<const float4*>(x + (size_t)n * ND);
                const float4* ar = reinterpret_cast<const float4*>(g_agg + (size_t)n * HID);
#pragma unroll
                for (int i = 0; i < 4; i++) {
                    const int f4 = q + 4 * i;
                    const int k  = f4 * 4;
                    float4 v = xr[f4];
                    sIn[(k + 0) * TILE_N + ng] = v.x;
                    sIn[(k + 1) * TILE_N + ng] = v.y;
                    sIn[(k + 2) * TILE_N + ng] = v.z;
                    sIn[(k + 3) * TILE_N + ng] = v.w;
                    float4 w = ar[f4];
                    sIn[(ND + k + 0) * TILE_N + ng] = w.x * inv + sB2[k + 0] * f;
                    sIn[(ND + k + 1) * TILE_N + ng] = w.y * inv + sB2[k + 1] * f;
                    sIn[(ND + k + 2) * TILE_N + ng] = w.z * inv + sB2[k + 2] * f;
                    sIn[(ND + k + 3) * TILE_N + ng] = w.w * inv + sB2[k + 3] * f;
                }
            }
        }
        __syncthreads();

        float acc[4][4];
#pragma unroll
        for (int a = 0; a < 4; a++)
#pragma unroll
            for (int b = 0; b < 4; b++) acc[a][b] = 0.f;

#pragma unroll 8
        for (int k = 0; k < 2 * ND; k++) {
            float4 av = *reinterpret_cast<const float4*>(&sIn[k * TILE_N + tx * 4]);
            float4 bv = *reinterpret_cast<const float4*>(&sWu[k * HID + ty * 4]);
            FMA16(acc, av, bv)
        }

#pragma unroll
        for (int ei = 0; ei < 4; ei++) {
            const int n = n0 + tx * 4 + ei;
            if (n < N) {
                float4 o;
                float r;
                r = acc[ei][0] + sBu[ty * 4 + 0];
                o.x = sIn[(ty * 4 + 0) * TILE_N + tx * 4 + ei] + (r > 0.f ? r : 0.f);
                r = acc[ei][1] + sBu[ty * 4 + 1];
                o.y = sIn[(ty * 4 + 1) * TILE_N + tx * 4 + ei] + (r > 0.f ? r : 0.f);
                r = acc[ei][2] + sBu[ty * 4 + 2];
                o.z = sIn[(ty * 4 + 2) * TILE_N + tx * 4 + ei] + (r > 0.f ? r : 0.f);
                r = acc[ei][3] + sBu[ty * 4 + 3];
                o.w = sIn[(ty * 4 + 3) * TILE_N + tx * 4 + ei] + (r > 0.f ? r : 0.f);
                *reinterpret_cast<float4*>(out + (size_t)n * HID + ty * 4) = o;
            }
        }
        __syncthreads();
    }
}

// ---------------------------------------------------------------------------
extern "C" void kernel_launch(void* const* d_in, const int* in_sizes, int n_in,
                              void* d_out, int out_size) {
    const float* x   = (const float*)d_in[0];
    const int*   ei  = (const int*)d_in[1];
    const float* ea  = (const float*)d_in[2];
    const float* W1  = (const float*)d_in[3];
    const float* b1  = (const float*)d_in[4];
    const float* W2  = (const float*)d_in[5];
    const float* b2  = (const float*)d_in[6];
    const float* Wu  = (const float*)d_in[7];
    const float* bu  = (const float*)d_in[8];
    float* out = (float*)d_out;

    const int N = in_sizes[0] / ND;     // 100000
    const int E = in_sizes[2] / EDIM;   // 1600000

    const int smem_pq   = (2 * 64 * LDW_H + 8 * 16 * LDX_H) * 2;
    const int smem_edge = (16 * LDW_H + HID * LDW_H + 16 * 32 * LDIN_H) * 2 +
                          512 * 4;
    const int smem_node = (2 * ND * HID + 2 * ND * TILE_N + 2 * HID) * 4;

    cudaFuncSetAttribute(pq_kernel, cudaFuncAttributeMaxDynamicSharedMemorySize,
                         smem_pq);
    cudaFuncSetAttribute(edge_kernel, cudaFuncAttributeMaxDynamicSharedMemorySize,
                         smem_edge);
    cudaFuncSetAttribute(node_kernel, cudaFuncAttributeMaxDynamicSharedMemorySize,
                         smem_node);

    const int npq = (N + 15) / 16;      // 16-node warp tiles
    const int nst = (E + 15) / 16;      // 16-edge stage tiles
    const int ntiles = (N + TILE_N - 1) / TILE_N;

    zero_kernel<<<2048, 256>>>(N);
    pq_kernel<<<(npq + 7) / 8, 256, smem_pq>>>(x, W1, N, npq);
    edge_kernel<<<148, 512, smem_edge>>>(ei, ea, W1, b1, W2, E, nst);
    node_kernel<<<456, 256, smem_node>>>(x, Wu, bu, b2, out, N, ntiles);
}